// round 13
// baseline (speedup 1.0000x reference)
#include <cuda_runtime.h>
#include <cuda_bf16.h>
#include <cstdint>

#define EMBED 100
#define BATCH 8192
#define MAT_FLOATS (EMBED * EMBED)     // 10000
#define MAT_BYTES  (MAT_FLOATS * 4)    // 40000
#define VEC4_PER_MAT 2500
#define F4_PER_ROW   25
#define NTHREADS     256
#define ITERS        10
#define GRID         296               // 2 CTAs per SM x 148 SMs, one wave

// smem layout (dynamic, ~81.7 KB): two 40KB matrix stages + double-buffered
// vectors + reduction scratch + 2 mbarriers.
#define OFF_MAT0 0
#define OFF_MAT1 40000
#define OFF_ARG  80000     // float[2][100]
#define OFF_CTX  80800     // float[2][100]
#define OFF_RED  81600     // float[8]
#define OFF_MBAR 81632     // uint64[2]
#define SMEM_TOTAL 81664

#define MBARRIER_WAIT_PARITY(mbar_smem_addr, phase_parity) do { \
    uint32_t _mbar = (uint32_t)(mbar_smem_addr); \
    uint32_t _parity = (uint32_t)(phase_parity); \
    uint32_t _done; \
    asm volatile( \
        "{\n\t" \
        ".reg .pred p;\n\t" \
        "mbarrier.try_wait.parity.acquire.cta.shared::cta.b64 p, [%1], %2;\n\t" \
        "selp.b32 %0, 1, 0, p;\n\t" \
        "}" \
        : "=r"(_done) : "r"(_mbar), "r"(_parity) : "memory"); \
    if (!_done) { \
        asm volatile( \
            "{\n\t" \
            ".reg .pred P1;\n\t" \
            "WAIT_LOOP_%=:\n\t" \
            "mbarrier.try_wait.parity.acquire.cta.shared::cta.b64 P1, [%0], %1, 0x989680;\n\t" \
            "@P1 bra.uni WAIT_DONE_%=;\n\t" \
            "bra.uni WAIT_LOOP_%=;\n\t" \
            "WAIT_DONE_%=:\n\t" \
            "}" \
            :: "r"(_mbar), "r"(_parity) : "memory"); \
    } \
} while(0)

__device__ __forceinline__ void tma_bulk_load(uint32_t dst_smem, const float* src,
                                              uint32_t mbar)
{
    asm volatile("mbarrier.arrive.expect_tx.shared.b64 _, [%0], %1;"
                 :: "r"(mbar), "r"((uint32_t)MAT_BYTES) : "memory");
    asm volatile("cp.async.bulk.shared::cta.global.mbarrier::complete_tx::bytes "
                 "[%0], [%1], %2, [%3];"
                 :: "r"(dst_smem), "l"(src), "r"((uint32_t)MAT_BYTES), "r"(mbar)
                 : "memory");
}

__global__ __launch_bounds__(NTHREADS)
void matrix_skipgram_persistent(const int* __restrict__ X_argument,
                                const int* __restrict__ X_functor,
                                const int* __restrict__ X_context,
                                const float* __restrict__ noun_matrix,
                                const float* __restrict__ functor_table,
                                const float* __restrict__ context_table,
                                float* __restrict__ out)
{
    extern __shared__ __align__(16) unsigned char smem[];
    float* s_mat[2] = { (float*)(smem + OFF_MAT0), (float*)(smem + OFF_MAT1) };
    float* s_arg    = (float*)(smem + OFF_ARG);
    float* s_ctx    = (float*)(smem + OFF_CTX);
    float* s_red    = (float*)(smem + OFF_RED);

    const int t   = threadIdx.x;
    const int bid = blockIdx.x;
    const uint32_t mb_base = (uint32_t)__cvta_generic_to_shared(smem + OFF_MBAR);
    const uint32_t mb[2]   = { mb_base, mb_base + 8 };
    const uint32_t mat_sm[2] = {
        (uint32_t)__cvta_generic_to_shared(smem + OFF_MAT0),
        (uint32_t)__cvta_generic_to_shared(smem + OFF_MAT1)
    };

    if (t == 0) {
        asm volatile("mbarrier.init.shared.b64 [%0], %1;" :: "r"(mb[0]), "r"(1) : "memory");
        asm volatile("mbarrier.init.shared.b64 [%0], %1;" :: "r"(mb[1]), "r"(1) : "memory");
        asm volatile("fence.proxy.async.shared::cta;" ::: "memory");
    }
    __syncthreads();

    // Prologue: launch loads for iterations 0 and 1; stage vectors for iter 0.
    if (t == 0) {
        tma_bulk_load(mat_sm[0], functor_table + (size_t)X_functor[bid] * MAT_FLOATS, mb[0]);
        if (bid + GRID < BATCH)
            tma_bulk_load(mat_sm[1], functor_table + (size_t)X_functor[bid + GRID] * MAT_FLOATS, mb[1]);
    }
    if (t < EMBED) {
        s_arg[t] = noun_matrix  [(size_t)X_argument[bid] * EMBED + t];
        s_ctx[t] = context_table[(size_t)X_context[bid]  * EMBED + t];
    }
    __syncthreads();   // vec(0) visible

    int ph0 = 0, ph1 = 0;
    int it = 0;
    for (int b = bid; b < BATCH; b += GRID, ++it) {
        const int s = it & 1;
        if (s == 0) { MBARRIER_WAIT_PARITY(mb[0], ph0); ph0 ^= 1; }
        else        { MBARRIER_WAIT_PARITY(mb[1], ph1); ph1 ^= 1; }

        // Prefetch next iteration's vectors into the other buffer
        // (overlaps with this iteration's compute; visible after the sync below).
        const int bn = b + GRID;
        if (bn < BATCH && t < EMBED) {
            s_arg[(s ^ 1) * EMBED + t] = noun_matrix  [(size_t)X_argument[bn] * EMBED + t];
            s_ctx[(s ^ 1) * EMBED + t] = context_table[(size_t)X_context[bn]  * EMBED + t];
        }

        const float4* __restrict__ Ms = reinterpret_cast<const float4*>(s_mat[s]);
        const float* va = s_arg + s * EMBED;
        const float* vc = s_ctx + s * EMBED;

        float acc = 0.0f;
        #pragma unroll
        for (int itk = 0; itk < ITERS; ++itk) {
            const int k = t + itk * NTHREADS;
            if (k < VEC4_PER_MAT) {
                const int i  = k / F4_PER_ROW;
                const int j4 = (k - i * F4_PER_ROW) * 4;
                const float4 m = Ms[k];
                float dot = m.x * va[j4] + m.y * va[j4 + 1]
                          + m.z * va[j4 + 2] + m.w * va[j4 + 3];
                acc = fmaf(vc[i], dot, acc);
            }
        }

        #pragma unroll
        for (int o = 16; o > 0; o >>= 1)
            acc += __shfl_xor_sync(0xFFFFFFFFu, acc, o);
        if ((t & 31) == 0) s_red[t >> 5] = acc;
        __syncthreads();
        if (t < (NTHREADS / 32)) {
            float r = s_red[t];
            #pragma unroll
            for (int o = (NTHREADS / 64); o > 0; o >>= 1)
                r += __shfl_xor_sync(0xFFu, r, o);
            if (t == 0) out[b] = r;
        }
        __syncthreads();   // everyone done with stage s matrix, s_red, and vec STS landed

        // Refill this stage with the matrix two iterations ahead.
        const int b2 = b + 2 * GRID;
        if (t == 0 && b2 < BATCH)
            tma_bulk_load(mat_sm[s], functor_table + (size_t)X_functor[b2] * MAT_FLOATS, mb[s]);
    }
}

extern "C" void kernel_launch(void* const* d_in, const int* in_sizes, int n_in,
                              void* d_out, int out_size)
{
    const int*   X_argument    = (const int*)  d_in[0];
    const int*   X_functor     = (const int*)  d_in[1];
    const int*   X_context     = (const int*)  d_in[2];
    const float* noun_matrix   = (const float*)d_in[3];
    const float* functor_table = (const float*)d_in[4];
    const float* context_table = (const float*)d_in[5];
    float* out = (float*)d_out;

    static int configured = 0;
    if (!configured) {
        cudaFuncSetAttribute(matrix_skipgram_persistent,
                             cudaFuncAttributeMaxDynamicSharedMemorySize, SMEM_TOTAL);
        configured = 1;
    }

    matrix_skipgram_persistent<<<GRID, NTHREADS, SMEM_TOTAL>>>(
        X_argument, X_functor, X_context,
        noun_matrix, functor_table, context_table, out);
}

// round 14
// speedup vs baseline: 1.5818x; 1.5818x over previous
#include <cuda_runtime.h>
#include <cuda_bf16.h>
#include <cstdint>

#define EMBED 100
#define BATCH 8192
#define MAT_FLOATS (EMBED * EMBED)
#define VEC4_PER_MAT 2500   // 100*100/4
#define F4_PER_ROW   25     // 100/4
#define NTHREADS     256
#define ITERS        10     // ceil(2500/256); iters 0..8 always in-bounds
#define GRID         888    // 6 CTAs/SM x 148 SMs -> single wave, persistent

__global__ __launch_bounds__(NTHREADS, 6)
void matrix_skipgram_kernel(const int* __restrict__ X_argument,
                            const int* __restrict__ X_functor,
                            const int* __restrict__ X_context,
                            const float* __restrict__ noun_matrix,
                            const float* __restrict__ functor_table,
                            const float* __restrict__ context_table,
                            float* __restrict__ out)
{
    __shared__ float s_arg[2][EMBED];
    __shared__ float s_ctx[2][EMBED];
    __shared__ float s_red[NTHREADS / 32];

    const int t = threadIdx.x;
    int b = blockIdx.x;

    // Prologue: stage element 0's functor id and vectors.
    int f_cur = X_functor[b];
    if (t < EMBED) {
        s_arg[0][t] = noun_matrix  [(size_t)X_argument[b] * EMBED + t];
        s_ctx[0][t] = context_table[(size_t)X_context[b]  * EMBED + t];
    }
    __syncthreads();

    int buf = 0;
    while (b < BATCH) {
        // 1) Front-batch this element's matrix: 10 independent LDG.128/thread.
        const float4* __restrict__ M =
            reinterpret_cast<const float4*>(functor_table + (size_t)f_cur * MAT_FLOATS);
        const int k9  = t + 9 * NTHREADS;
        const bool v9 = (k9 < VEC4_PER_MAT);
        float4 m[ITERS];
        #pragma unroll
        for (int it = 0; it < ITERS - 1; ++it)
            m[it] = __ldg(&M[t + it * NTHREADS]);
        m[ITERS - 1] = __ldg(&M[v9 ? k9 : 0]);

        // 2) Prefetch next element (indices + vectors) while loads fly.
        const int bn = b + GRID;
        int f_next = 0;
        if (bn < BATCH) {
            f_next = X_functor[bn];   // uniform across CTA: one broadcast sector
            if (t < EMBED) {
                s_arg[buf ^ 1][t] = noun_matrix  [(size_t)X_argument[bn] * EMBED + t];
                s_ctx[buf ^ 1][t] = context_table[(size_t)X_context[bn]  * EMBED + t];
            }
        }

        // 3) Compute from registers + current vector buffer.
        const float* va = s_arg[buf];
        const float* vc = s_ctx[buf];
        float acc = 0.0f;
        #pragma unroll
        for (int it = 0; it < ITERS - 1; ++it) {
            const int k  = t + it * NTHREADS;
            const int i  = k / F4_PER_ROW;
            const int j4 = (k - i * F4_PER_ROW) * 4;
            float dot = m[it].x * va[j4]     + m[it].y * va[j4 + 1]
                      + m[it].z * va[j4 + 2] + m[it].w * va[j4 + 3];
            acc = fmaf(vc[i], dot, acc);
        }
        {   // masked last iteration
            const int k  = v9 ? k9 : 0;
            const int i  = k / F4_PER_ROW;
            const int j4 = (k - i * F4_PER_ROW) * 4;
            float dot = m[ITERS - 1].x * va[j4]     + m[ITERS - 1].y * va[j4 + 1]
                      + m[ITERS - 1].z * va[j4 + 2] + m[ITERS - 1].w * va[j4 + 3];
            acc = fmaf(v9 ? vc[i] : 0.0f, dot, acc);
        }

        // 4) Reduce and store.
        #pragma unroll
        for (int o = 16; o > 0; o >>= 1)
            acc += __shfl_xor_sync(0xFFFFFFFFu, acc, o);
        if ((t & 31) == 0) s_red[t >> 5] = acc;
        __syncthreads();
        if (t < (NTHREADS / 32)) {
            float r = s_red[t];
            #pragma unroll
            for (int o = (NTHREADS / 64); o > 0; o >>= 1)
                r += __shfl_xor_sync(0xFFu, r, o);
            if (t == 0) out[b] = r;
        }
        __syncthreads();   // protects s_red AND publishes buf^1 vectors

        f_cur = f_next;
        buf ^= 1;
        b = bn;
    }
}

extern "C" void kernel_launch(void* const* d_in, const int* in_sizes, int n_in,
                              void* d_out, int out_size)
{
    const int*   X_argument    = (const int*)  d_in[0];
    const int*   X_functor     = (const int*)  d_in[1];
    const int*   X_context     = (const int*)  d_in[2];
    const float* noun_matrix   = (const float*)d_in[3];
    const float* functor_table = (const float*)d_in[4];
    const float* context_table = (const float*)d_in[5];
    float* out = (float*)d_out;

    matrix_skipgram_kernel<<<GRID, NTHREADS>>>(
        X_argument, X_functor, X_context,
        noun_matrix, functor_table, context_table, out);
}